// round 10
// baseline (speedup 1.0000x reference)
#include <cuda_runtime.h>
#include <cstdint>
#include <cstddef>
#include <math.h>

#define NDIM 8192
#define CDIM 16
#define KSEL 131072u
#define MAXDEG 64
#define CAP 512
#define CAND_CAP 33554432u    // 2^25 >= N(N-1)/2 pairs -> full fallback always fits
#define LOOP_BLOCKS 148
#define NTILES 8256           // 128*129/2 upper-triangular 64x64 tiles
#define S_PIV 1.6f            // collection pivot on s = a1+a2
#define A_PIV 0.9f            // collection pivot on a1 (covers skip branch)

static constexpr size_t NSLOTS = (size_t)NDIM * (size_t)CAP;

// ---------------- device scratch ----------------
__device__ unsigned long long g_buf[CAND_CAP];      // (pBits<<32)|flatIdx
__device__ unsigned int  g_candIdx[CAND_CAP];       // bit31=sameflag, low 26 = flatIdx
__device__ float2        g_candVal[CAND_CAP];       // (a1, a2)
__device__ unsigned int  g_candCnt;
__device__ unsigned int  g_bufCnt;
__device__ unsigned char g_labels8[NDIM];
__device__ double        g_sameMass, g_totMass;
__device__ float         g_wsame, g_wdiff;
__device__ int           g_skip;
__device__ unsigned int  g_hist1[4096], g_hist2[4096], g_hist3[256];
__device__ int           g_nbr[NSLOTS];
__device__ float         g_pf[NSLOTS];
__device__ float         g_pr[NSLOTS];
__device__ unsigned char g_act[NSLOTS];
__device__ int           g_deg[NDIM];
__device__ unsigned int  g_thrU[NDIM];
__device__ unsigned char g_keepall[NDIM];
__device__ unsigned int  g_eqIdx[KSEL];
__device__ unsigned int  g_eqCnt;
__device__ unsigned int  g_changedArr[12];
__device__ unsigned int  g_tk[4];
__device__ unsigned int  g_barCount, g_barGen;

// ---------------- grid barrier (148 co-resident blocks) ----------------
__device__ __forceinline__ void gridBar() {
    __threadfence();
    __syncthreads();
    if (threadIdx.x == 0) {
        unsigned gen = atomicAdd(&g_barGen, 0u);
        if (atomicAdd(&g_barCount, 1u) == LOOP_BLOCKS - 1) {
            g_barCount = 0u;
            __threadfence();
            atomicAdd(&g_barGen, 1u);
        } else {
            unsigned spins = 0;
            while (atomicAdd(&g_barGen, 0u) == gen) {
                if (++spins > (1u << 28)) break;
                __nanosleep(64);
            }
        }
    }
    __syncthreads();
}

// Boundary-bin search over 4096 bins, 1024 threads, shfl-based.
__device__ void scanSelect4096(const unsigned* hist, unsigned baseCum,
                               unsigned* outBin, unsigned* outCntGt) {
    __shared__ unsigned warpAbv[32];
    int t = threadIdx.x;
    int lane = t & 31, w = t >> 5;
    unsigned local[4];
    unsigned s = 0;
#pragma unroll
    for (int k = 0; k < 4; k++) { local[k] = __ldcg(&hist[t * 4 + k]); s += local[k]; }
    unsigned rs = s;
#pragma unroll
    for (int d = 1; d < 32; d <<= 1) {
        unsigned v = __shfl_down_sync(0xFFFFFFFFu, rs, d);
        if (lane + d < 32) rs += v;
    }
    if (lane == 0) warpAbv[w] = rs;
    __syncthreads();
    if (w == 0) {
        unsigned ws = warpAbv[lane];
        unsigned rws = ws;
#pragma unroll
        for (int d = 1; d < 32; d <<= 1) {
            unsigned v = __shfl_down_sync(0xFFFFFFFFu, rws, d);
            if (lane + d < 32) rws += v;
        }
        warpAbv[lane] = rws - ws;
    }
    __syncthreads();
    unsigned cum = baseCum + warpAbv[w] + (rs - s);
#pragma unroll
    for (int k = 3; k >= 0; k--) {
        unsigned h = local[k];
        unsigned cg = cum + h;
        if (cg >= KSEL && cum < KSEL) { *outBin = (unsigned)(t * 4 + k); *outCntGt = cum; }
        cum = cg;
    }
    __syncthreads();
}

__device__ void scanSelect256(const unsigned* hist, unsigned baseCum, unsigned prefix12,
                              unsigned* outThr, unsigned* outNeed) {
    __shared__ unsigned wAbv2[8];
    int t = threadIdx.x;
    int lane = t & 31, w = t >> 5;
    unsigned h = (t < 256) ? __ldcg(&hist[t]) : 0u;
    unsigned rs = h;
#pragma unroll
    for (int d = 1; d < 32; d <<= 1) {
        unsigned v = __shfl_down_sync(0xFFFFFFFFu, rs, d);
        if (lane + d < 32) rs += v;
    }
    if (w < 8 && lane == 0) wAbv2[w] = rs;
    __syncthreads();
    if (t == 0) {
        unsigned c = 0;
        for (int k = 7; k >= 0; k--) { unsigned v = wAbv2[k]; wAbv2[k] = c; c += v; }
    }
    __syncthreads();
    if (t < 256) {
        unsigned cum = baseCum + wAbv2[w] + (rs - h);
        unsigned cg = cum + h;
        if (cg >= KSEL && cum < KSEL) {
            *outThr = (prefix12 << 8) | (unsigned)t;
            *outNeed = KSEL - cum;
        }
    }
    __syncthreads();
}

// ---------------- init: clear (block 32) + argmax (blocks 0..31) ----------------
__global__ void initK(const float* __restrict__ lp) {
    int t = threadIdx.x;
    if (blockIdx.x == 32) {
        for (int k = t; k < 4096; k += 256) { g_hist1[k] = 0; g_hist2[k] = 0; }
        if (t < 256) g_hist3[t] = 0;
        for (int k = t; k < NDIM; k += 256) g_deg[k] = 0;
        if (t < 12) g_changedArr[t] = 0;
        if (t < 4)  g_tk[t] = 0;
        if (t == 0) {
            g_candCnt = 0; g_bufCnt = 0; g_eqCnt = 0;
            g_sameMass = 0.0; g_totMass = 0.0;
        }
        return;
    }
    int i = blockIdx.x * 256 + t;
    float best = lp[(size_t)i * CDIM];
    int bi = 0;
#pragma unroll
    for (int c = 1; c < CDIM; c++) {
        float v = lp[(size_t)i * CDIM + c];
        if (v > best) { best = v; bi = c; }
    }
    g_labels8[i] = (unsigned char)bi;
}

// ---------------- ONE fused pass: masses + candidate collection ----------------
// Reads each matrix element exactly once (tile + transpose per unordered pair).
// Collects (i,j,a1,a2,same) for s=a1+a2 >= S_PIV or a1 >= A_PIV. For w <= CLAMP=3,
// p <= 1.5*s*(1+2.1*2^-24) < 2.4001 for non-collected -> verified post-radix.
__global__ void fusedK(const float* __restrict__ adj) {
    int tt = blockIdx.x;
    int bi = (int)((257.0 - sqrt(257.0 * 257.0 - 8.0 * (double)tt)) * 0.5);
    if (bi > 127) bi = 127;
    if (bi < 0) bi = 0;
    while (bi > 0 && (bi * (257 - bi)) / 2 > tt) bi--;
    while (((bi + 1) * (257 - (bi + 1))) / 2 <= tt) bi++;
    int bj = bi + (tt - (bi * (257 - bi)) / 2);

    __shared__ float sA[64][65];     // direct tile  [row r in bi-block][col c in bj-block]
    __shared__ float sAt[64][65];    // transpose tile [row r2 in bj-block][col c2 in bi-block]
    __shared__ unsigned char slj[64];
    __shared__ unsigned short sMask[64][4];
    __shared__ unsigned warpTot[8], warpBase[8];
    __shared__ unsigned blockBase;
    __shared__ double ssh[256], sth[256];
    int t = threadIdx.x;
    const bool isDiag = (bi == bj);

    if (t < 64) slj[t] = g_labels8[bj * 64 + t];
    for (int e = t; e < 64 * 16; e += 256) {
        int r = e >> 4, c4 = (e & 15) * 4;
        float4 v = __ldcs((const float4*)(adj + (size_t)(bi * 64 + r) * NDIM + bj * 64 + c4));
        sA[r][c4] = v.x; sA[r][c4 + 1] = v.y; sA[r][c4 + 2] = v.z; sA[r][c4 + 3] = v.w;
        float4 u = __ldcs((const float4*)(adj + (size_t)(bj * 64 + r) * NDIM + bi * 64 + c4));
        sAt[r][c4] = u.x; sAt[r][c4 + 1] = u.y; sAt[r][c4 + 2] = u.z; sAt[r][c4 + 3] = u.w;
    }
    __syncthreads();
    {
        int r = t >> 2, q = t & 3;
        unsigned char lr = g_labels8[bi * 64 + r];
        unsigned short m = 0;
#pragma unroll
        for (int cc = 0; cc < 16; cc++)
            m |= (unsigned short)((lr == slj[q * 16 + cc]) ? 1 : 0) << cc;
        sMask[r][q] = m;
    }
    __syncthreads();

    // pass 1: masses + candidate count
    float fs = 0.f, ft = 0.f;
    int cnt = 0;
    for (int e = t; e < 4096; e += 256) {
        int r = e >> 6, c = e & 63;
        if (isDiag && c <= r) continue;
        float a1 = sA[r][c], a2 = sAt[c][r];
        float s2 = a1 + a2;
        ft += s2;
        if ((sMask[r][c >> 4] >> (c & 15)) & 1) fs += s2;
        if (s2 >= S_PIV || a1 >= A_PIV) cnt++;
    }
    if (isDiag && t < 64) ft += sA[t][t];   // diagonal: diff-class mass only

    // block-aggregated candidate append offsets
    unsigned pre = (unsigned)cnt;
    for (int d = 1; d < 32; d <<= 1) {
        unsigned v = __shfl_up_sync(0xFFFFFFFFu, pre, d);
        if ((t & 31) >= d) pre += v;
    }
    if ((t & 31) == 31) warpTot[t >> 5] = pre;
    __syncthreads();
    if (t == 0) {
        unsigned s = 0;
        for (int w = 0; w < 8; w++) { unsigned v = warpTot[w]; warpBase[w] = s; s += v; }
        blockBase = s ? atomicAdd(&g_candCnt, s) : 0u;
    }
    __syncthreads();
    unsigned pos = blockBase + warpBase[t >> 5] + (pre - (unsigned)cnt);

    // pass 2: write candidates (same element order as count)
    for (int e = t; e < 4096; e += 256) {
        int r = e >> 6, c = e & 63;
        if (isDiag && c <= r) continue;
        float a1 = sA[r][c], a2 = sAt[c][r];
        float s2 = a1 + a2;
        if (s2 >= S_PIV || a1 >= A_PIV) {
            unsigned same = (sMask[r][c >> 4] >> (c & 15)) & 1u;
            int i = bi * 64 + r, j = bj * 64 + c;
            if (pos < CAND_CAP) {
                g_candIdx[pos] = (unsigned)(i * NDIM + j) | (same << 31);
                g_candVal[pos] = make_float2(a1, a2);
            }
            pos++;
        }
    }

    // mass reduction + ticketed decide
    ssh[t] = (double)fs; sth[t] = (double)ft;
    __syncthreads();
    for (int off = 128; off > 0; off >>= 1) {
        if (t < off) { ssh[t] += ssh[t + off]; sth[t] += sth[t + off]; }
        __syncthreads();
    }
    if (t == 0) {
        atomicAdd(&g_sameMass, ssh[0]);
        atomicAdd(&g_totMass, sth[0]);
        __threadfence();
        if (atomicAdd(&g_tk[0], 1u) == gridDim.x - 1) {
            double sm = g_sameMass, tm = g_totMass;
            double dm = tm - sm;
            float cur = (float)(sm / tm);
            g_wsame = fminf(fmaxf(0.7f / (cur + 1e-6f), (float)(1.0 / 3.0)), 3.0f);
            g_wdiff = fminf(fmaxf(0.3f / (1.0f - cur + 1e-6f), (float)(1.0 / 3.0)), 3.0f);
            g_skip = (sm <= 1e-6 || dm <= 1e-6 || fabsf(cur - 0.7f) <= 0.05f) ? 1 : 0;
        }
    }
}

// ---------------- edge emission ----------------
__device__ __forceinline__ void emitEdge(int i, int j, float p,
                                         const float* __restrict__ adj, int skip) {
    float pf_i, pr_i, pf_j, pr_j;
    if (skip) {
        float aij = adj[(size_t)i * NDIM + j];
        float aji = adj[(size_t)j * NDIM + i];
        pf_i = aij; pr_i = aji; pf_j = aji; pr_j = aij;
    } else {
        pf_i = pr_i = pf_j = pr_j = p;
    }
    int di = atomicAdd(&g_deg[i], 1);
    if (di < CAP) {
        size_t s = (size_t)i * CAP + di;
        g_nbr[s] = j; g_pf[s] = pf_i; g_pr[s] = pr_i; g_act[s] = 1;
    }
    int dj = atomicAdd(&g_deg[j], 1);
    if (dj < CAP) {
        size_t s = (size_t)j * CAP + dj;
        g_nbr[s] = i; g_pf[s] = pf_j; g_pr[s] = pr_j; g_act[s] = 1;
    }
}

// Fallback: append p for every pair NOT collected (exact complement predicate).
__device__ void fallbackF(const float* __restrict__ adj, int skip, float ws, float wd, int t) {
    for (int tile = blockIdx.x; tile < 128 * 128; tile += LOOP_BLOCKS) {
        int bi = tile >> 7, bj = tile & 127;
        if (bj < bi) continue;
        for (int e = t; e < 4096; e += 1024) {
            int i = bi * 64 + (e >> 6), j = bj * 64 + (e & 63);
            if (j <= i) continue;
            float a1 = adj[(size_t)i * NDIM + j];
            float a2 = adj[(size_t)j * NDIM + i];
            float s2 = a1 + a2;
            if (s2 >= S_PIV || a1 >= A_PIV) continue;   // already collected
            float p;
            if (skip) p = a1;
            else {
                float w = (g_labels8[i] == g_labels8[j]) ? ws : wd;
                p = 0.5f * __fadd_rn(__fmul_rn(a1, w), __fmul_rn(a2, w));
            }
            unsigned pos = atomicAdd(&g_bufCnt, 1u);
            if (pos < CAND_CAP)
                g_buf[pos] = ((unsigned long long)__float_as_uint(p) << 32)
                             | (unsigned)(i * NDIM + j);
        }
    }
}

// ---------------- persistent tail ----------------
__global__ void __launch_bounds__(1024, 1) postK(const float* __restrict__ adj,
                                                 float* __restrict__ out) {
    __shared__ unsigned shH[4096];
    __shared__ unsigned shO[8192];
    __shared__ unsigned sBA, sCntA, sBinB, sCntB, sBAB, sThr, sNeed;
    int t = threadIdx.x;
    if (t == 0) { sThr = 0xFFFFFFFFu; sNeed = 0u; }
    __syncthreads();

    int skip = g_skip;
    float ws = g_wsame, wd = g_wdiff;

    // phase P0: compute p for candidates, build radix buffer
    unsigned nc = min(__ldcg(&g_candCnt), CAND_CAP);
    for (unsigned c = blockIdx.x * 1024u + t; c < nc; c += LOOP_BLOCKS * 1024u) {
        unsigned rec = __ldcg(&g_candIdx[c]);
        float2 av = __ldcg(&g_candVal[c]);
        float p;
        if (skip) p = av.x;
        else {
            float w = (rec >> 31) ? ws : wd;
            p = 0.5f * __fadd_rn(__fmul_rn(av.x, w), __fmul_rn(av.y, w));
        }
        g_buf[c] = ((unsigned long long)__float_as_uint(p) << 32) | (rec & 0x03FFFFFFu);
    }
    if (blockIdx.x == 0 && t == 0) g_bufCnt = nc;
    gridBar();

    // radix selection with verified completeness + exact fallback
    unsigned boundBits = skip ? __float_as_uint(A_PIV) : __float_as_uint(2.4001f);
    bool didF = false;
    bool needF = (__ldcg(&g_bufCnt) < KSEL);
    unsigned n = 0;
    for (int pass = 0; pass < 2; pass++) {
        if (needF && !didF) {
            fallbackF(adj, skip, ws, wd, t);
            didF = true;
            gridBar();
            // clear hists (may hold a failed pass's content)
            for (unsigned k = blockIdx.x * 1024u + t; k < 8448; k += LOOP_BLOCKS * 1024u) {
                if (k < 4096) __stcg(&g_hist1[k], 0u);
                else if (k < 8192) __stcg(&g_hist2[k - 4096], 0u);
                else __stcg(&g_hist3[k - 8192], 0u);
            }
            gridBar();
        }
        needF = false;
        n = min(__ldcg(&g_bufCnt), CAND_CAP);

        // H1
        for (int k = t; k < 4096; k += 1024) shH[k] = 0;
        __syncthreads();
        for (unsigned idx = blockIdx.x * 1024u + t; idx < n; idx += LOOP_BLOCKS * 1024u)
            atomicAdd(&shH[(unsigned)(__ldcg(&g_buf[idx]) >> 32) >> 20], 1u);
        __syncthreads();
        for (int k = t; k < 4096; k += 1024)
            if (shH[k]) atomicAdd(&g_hist1[k], shH[k]);
        gridBar();
        scanSelect4096(g_hist1, 0u, &sBA, &sCntA);

        // H2
        for (int k = t; k < 4096; k += 1024) shH[k] = 0;
        __syncthreads();
        {
            unsigned bA = sBA;
            for (unsigned idx = blockIdx.x * 1024u + t; idx < n; idx += LOOP_BLOCKS * 1024u) {
                unsigned bits = (unsigned)(__ldcg(&g_buf[idx]) >> 32);
                if ((bits >> 20) == bA) atomicAdd(&shH[(bits >> 8) & 0xFFFu], 1u);
            }
        }
        __syncthreads();
        for (int k = t; k < 4096; k += 1024)
            if (shH[k]) atomicAdd(&g_hist2[k], shH[k]);
        gridBar();
        scanSelect4096(g_hist2, sCntA, &sBinB, &sCntB);
        if (t == 0) sBAB = (sBA << 12) | sBinB;
        __syncthreads();

        // H3
        if (t < 256) shH[t] = 0;
        __syncthreads();
        {
            unsigned bAB = sBAB;
            for (unsigned idx = blockIdx.x * 1024u + t; idx < n; idx += LOOP_BLOCKS * 1024u) {
                unsigned bits = (unsigned)(__ldcg(&g_buf[idx]) >> 32);
                if ((bits >> 8) == bAB) atomicAdd(&shH[bits & 0xFFu], 1u);
            }
        }
        __syncthreads();
        if (t < 256 && shH[t]) atomicAdd(&g_hist3[t], shH[t]);
        gridBar();
        scanSelect256(g_hist3, sCntB, sBAB, &sThr, &sNeed);

        if (didF || sThr >= boundBits) break;   // complete: non-collected p provably < thr
        needF = true;                           // else: exact fallback and redo
    }

    // phase S: select + emit
    {
        unsigned thr = sThr;
        for (unsigned idx = blockIdx.x * 1024u + t; idx < n; idx += LOOP_BLOCKS * 1024u) {
            unsigned long long e = __ldcg(&g_buf[idx]);
            unsigned bits = (unsigned)(e >> 32);
            if (bits > thr) {
                unsigned fi = (unsigned)e;
                emitEdge((int)(fi >> 13), (int)(fi & 8191u), __uint_as_float(bits), adj, skip);
            } else if (bits == thr) {
                unsigned pos = atomicAdd(&g_eqCnt, 1u);
                if (pos < KSEL) g_eqIdx[pos] = (unsigned)e;
            }
        }
    }
    gridBar();

    // phase T: tie resolution (lowest flat index wins)
    {
        unsigned M = min(__ldcg(&g_eqCnt), KSEL);
        unsigned need = sNeed;
        unsigned thr = sThr;
        if (need > 0) {
            for (unsigned u = blockIdx.x * 1024u + t; u < M; u += LOOP_BLOCKS * 1024u) {
                unsigned idx = __ldcg(&g_eqIdx[u]);
                unsigned rank = 0;
                for (unsigned s = 0; s < M; s++) rank += (__ldcg(&g_eqIdx[s]) < idx) ? 1u : 0u;
                if (rank < need)
                    emitEdge((int)(idx >> 13), (int)(idx & 8191u), __uint_as_float(thr), adj, skip);
            }
        }
    }
    gridBar();

    // phase P: degree-cap prune loop, warp per row, early exit on fixed point
    int lane = t & 31;
    int warpG = blockIdx.x * 32 + (t >> 5);
    const int nW = LOOP_BLOCKS * 32;
    __shared__ unsigned sCont;

    for (int iter = 0; iter < 10; iter++) {
        for (int i = warpG; i < NDIM; i += nW) {
            size_t base = (size_t)i * CAP;
            int degE = min(__ldcg(&g_deg[i]), CAP);
            float v[16]; unsigned am = 0, dc = 0;
#pragma unroll
            for (int k = 0; k < 16; k++) {
                int s = lane + k * 32;
                bool a = (s < degE) && (__ldcg(&g_act[base + s]) != 0);
                if (a) { v[k] = __ldcg(&g_pf[base + s]); am |= 1u << k; dc++; }
            }
            unsigned deg = __reduce_add_sync(0xFFFFFFFFu, dc);
            if (deg <= (unsigned)MAXDEG) {
                if (lane == 0) __stcg(&g_keepall[i], (unsigned char)1);
                continue;
            }
            if (lane == 0) __stcg(&g_keepall[i], (unsigned char)0);
            unsigned T = 0;
            for (int b = 31; b >= 0; b--) {
                unsigned cand = T | (1u << b);
                unsigned c = 0;
#pragma unroll
                for (int k = 0; k < 16; k++)
                    if (((am >> k) & 1u) && __float_as_uint(v[k]) >= cand) c++;
                c = __reduce_add_sync(0xFFFFFFFFu, c);
                if (c >= (unsigned)MAXDEG) T = cand;
            }
            if (lane == 0) __stcg(&g_thrU[i], T);
        }
        gridBar();
        bool removed = false;
        for (int i = warpG; i < NDIM; i += nW) {
            size_t base = (size_t)i * CAP;
            int degE = min(__ldcg(&g_deg[i]), CAP);
            unsigned kaI = __ldcg(&g_keepall[i]);
            unsigned thrI = __ldcg(&g_thrU[i]);
            for (int s = lane; s < degE; s += 32) {
                if (!__ldcg(&g_act[base + s])) continue;
                int j = __ldcg(&g_nbr[base + s]);
                bool ki = kaI || (__float_as_uint(__ldcg(&g_pf[base + s])) >= thrI);
                bool kj = __ldcg(&g_keepall[j]) ||
                          (__float_as_uint(__ldcg(&g_pr[base + s])) >= __ldcg(&g_thrU[j]));
                if (!(ki && kj)) { __stcg(&g_act[base + s], (unsigned char)0); removed = true; }
            }
        }
        if (__any_sync(0xFFFFFFFFu, removed) && lane == 0)
            atomicOr(&g_changedArr[iter + 1], 1u);
        gridBar();
        if (t == 0) sCont = __ldcg(&g_changedArr[iter + 1]);
        __syncthreads();
        if (!sCont) break;
    }

    // phase O: output — warp per row, __syncwarp only, coalesced stores
    {
        unsigned* wb = shO + ((t >> 5) << 8);
        for (int i = warpG; i < NDIM; i += nW) {
#pragma unroll
            for (int k = 0; k < 8; k++) wb[lane + k * 32] = 0u;
            __syncwarp();
            size_t base = (size_t)i * CAP;
            int degE = min(__ldcg(&g_deg[i]), CAP);
            for (int s = lane; s < degE; s += 32)
                if (__ldcg(&g_act[base + s])) {
                    int j = __ldcg(&g_nbr[base + s]);
                    atomicOr(&wb[j >> 5], 1u << (j & 31));
                }
            __syncwarp();
            float4* orow = (float4*)(out + (size_t)i * NDIM);
            for (int k = 0; k < 64; k++) {
                int q = k * 32 + lane;
                unsigned w = wb[q >> 3];
                unsigned sh = (q & 7) * 4;
                float4 v;
                v.x = (w >> sh & 1u) ? 1.f : 0.f;
                v.y = (w >> (sh + 1) & 1u) ? 1.f : 0.f;
                v.z = (w >> (sh + 2) & 1u) ? 1.f : 0.f;
                v.w = (w >> (sh + 3) & 1u) ? 1.f : 0.f;
                __stcs(&orow[q], v);
            }
            __syncwarp();
        }
    }
}

// ---------------- launch ----------------
extern "C" void kernel_launch(void* const* d_in, const int* in_sizes, int n_in,
                              void* d_out, int out_size) {
    const float* adj = (const float*)d_in[0];
    const float* lp  = (const float*)d_in[1];
    float* out = (float*)d_out;

    initK<<<33, 256>>>(lp);                    // clear + argmax fused
    fusedK<<<NTILES, 256>>>(adj);              // ONE matrix pass: masses + candidates
    postK<<<LOOP_BLOCKS, 1024>>>(adj, out);    // p-build + radix(+verify/fallback) + select + prune + output
}

// round 11
// speedup vs baseline: 1.2931x; 1.2931x over previous
#include <cuda_runtime.h>
#include <cstdint>
#include <cstddef>

#define NDIM 8192
#define CDIM 16
#define KSEL 131072u
#define MAXDEG 64
#define CAP 512
#define BUF_CAP 33554432u   // 2^25 >= N(N-1)/2 -> full fallback always fits
#define LOOP_BLOCKS 148

static constexpr size_t NN = (size_t)NDIM * (size_t)NDIM;
static constexpr size_t NSLOTS = (size_t)NDIM * (size_t)CAP;

// ---------------- device scratch ----------------
__device__ unsigned long long g_buf[BUF_CAP];
__device__ unsigned int  g_bufCnt;
__device__ unsigned char g_labels8[NDIM];
__device__ double        g_sameMass, g_totMass;
__device__ float         g_wsame, g_wdiff;
__device__ int           g_skip;
__device__ int           g_dSkip;          // diff-class pairs provably below pivot
__device__ unsigned int  g_maxA;           // max adj element (bit pattern, non-neg floats)
__device__ unsigned int  g_hist1[4096];
__device__ unsigned int  g_hist2[4096];
__device__ unsigned int  g_hist3[256];
__device__ int           g_nbr[NSLOTS];
__device__ float         g_pf[NSLOTS];
__device__ float         g_pr[NSLOTS];
__device__ unsigned char g_act[NSLOTS];
__device__ int           g_deg[NDIM];
__device__ unsigned int  g_thrU[NDIM];
__device__ unsigned char g_keepall[NDIM];
__device__ unsigned int  g_eqIdx[KSEL];
__device__ unsigned int  g_eqCnt;
__device__ unsigned int  g_changedArr[12];
__device__ unsigned int  g_tk[4];
__device__ unsigned int  g_barCount, g_barGen;

// ---------------- grid barrier (148 co-resident blocks) ----------------
__device__ __forceinline__ void gridBar() {
    __threadfence();
    __syncthreads();
    if (threadIdx.x == 0) {
        unsigned gen = atomicAdd(&g_barGen, 0u);
        if (atomicAdd(&g_barCount, 1u) == LOOP_BLOCKS - 1) {
            g_barCount = 0u;
            __threadfence();
            atomicAdd(&g_barGen, 1u);
        } else {
            unsigned spins = 0;
            while (atomicAdd(&g_barGen, 0u) == gen) {
                if (++spins > (1u << 28)) break;
                __nanosleep(64);
            }
        }
    }
    __syncthreads();
}

// Boundary-bin search over 4096 bins, 1024 threads, results into SHARED outputs.
// All blocks run this redundantly on identical global data.
__device__ void scanSelect4096(const unsigned* hist, unsigned baseCum,
                               unsigned* outBin, unsigned* outCntGt) {
    __shared__ unsigned part[1024];
    int t = threadIdx.x;
    unsigned local[4];
    unsigned s = 0;
#pragma unroll
    for (int k = 0; k < 4; k++) { local[k] = __ldcg(&hist[t * 4 + k]); s += local[k]; }
    part[t] = s;
    __syncthreads();
    for (int off = 1; off < 1024; off <<= 1) {
        unsigned v = (t + off < 1024) ? part[t + off] : 0u;
        __syncthreads();
        part[t] += v;
        __syncthreads();
    }
    unsigned cum = baseCum + ((t < 1023) ? part[t + 1] : 0u);
#pragma unroll
    for (int k = 3; k >= 0; k--) {
        unsigned h = local[k];
        unsigned cg = cum + h;
        if (cg >= KSEL && cum < KSEL) { *outBin = (unsigned)(t * 4 + k); *outCntGt = cum; }
        cum = cg;
    }
    __syncthreads();
}

__device__ void scanSelect256(const unsigned* hist, unsigned baseCum, unsigned prefix12,
                              unsigned* outThr, unsigned* outNeed) {
    __shared__ unsigned part2[1024];
    int t = threadIdx.x;
    unsigned h = (t < 256) ? __ldcg(&hist[t]) : 0u;
    part2[t] = h;
    __syncthreads();
    for (int off = 1; off < 1024; off <<= 1) {
        unsigned v = (t + off < 1024) ? part2[t + off] : 0u;
        __syncthreads();
        part2[t] += v;
        __syncthreads();
    }
    unsigned cum = baseCum + ((t < 1023) ? part2[t + 1] : 0u);
    unsigned cg = cum + h;
    if (t < 256 && cg >= KSEL && cum < KSEL) {
        *outThr = (prefix12 << 8) | (unsigned)t;
        *outNeed = KSEL - cum;
    }
    __syncthreads();
}

// ---------------- init: clear (block 32) + argmax (blocks 0..31) ----------------
__global__ void initK(const float* __restrict__ lp) {
    int t = threadIdx.x;
    if (blockIdx.x == 32) {
        for (int k = t; k < 4096; k += 256) { g_hist1[k] = 0; g_hist2[k] = 0; }
        if (t < 256) g_hist3[t] = 0;
        for (int k = t; k < NDIM; k += 256) g_deg[k] = 0;
        if (t < 12) g_changedArr[t] = 0;
        if (t < 4)  g_tk[t] = 0;
        if (t == 0) {
            g_bufCnt = 0; g_eqCnt = 0; g_maxA = 0; g_dSkip = 0;
            g_sameMass = 0.0; g_totMass = 0.0;
        }
        return;
    }
    int i = blockIdx.x * 256 + t;
    float best = lp[(size_t)i * CDIM];
    int bi = 0;
#pragma unroll
    for (int c = 1; c < CDIM; c++) {
        float v = lp[(size_t)i * CDIM + c];
        if (v > best) { best = v; bi = c; }
    }
    g_labels8[i] = (unsigned char)bi;
}

// ---------------- mass pass (+ max element); decide in last block ----------------
__global__ void massK(const float* __restrict__ adj) {
    __shared__ unsigned char slab[NDIM];
    __shared__ double ssh[256], sth[256];
    __shared__ unsigned smx[256];
    int i = blockIdx.x, t = threadIdx.x;
    for (int k = t; k < NDIM / 4; k += 256)
        ((unsigned*)slab)[k] = ((const unsigned*)g_labels8)[k];
    __syncthreads();
    unsigned li4 = (unsigned)slab[i] * 0x01010101u;
    const float4* row = (const float4*)(adj + (size_t)i * NDIM);
    float fs = 0.f, ft = 0.f, fm = 0.f;
    for (int q = t; q < NDIM / 4; q += 256) {
        float4 a = __ldcs(&row[q]);
        unsigned l4 = ((unsigned*)slab)[q];
        unsigned eq = __vcmpeq4(l4, li4);
        int j0 = q * 4;
        if (i >= j0 && i < j0 + 4) eq &= ~(0xFFu << ((i - j0) * 8));
        ft += a.x + a.y + a.z + a.w;
        fm = fmaxf(fm, fmaxf(fmaxf(a.x, a.y), fmaxf(a.z, a.w)));
        if (eq & 0x000000FFu) fs += a.x;
        if (eq & 0x0000FF00u) fs += a.y;
        if (eq & 0x00FF0000u) fs += a.z;
        if (eq & 0xFF000000u) fs += a.w;
    }
    ssh[t] = (double)fs; sth[t] = (double)ft; smx[t] = __float_as_uint(fmaxf(fm, 0.f));
    __syncthreads();
    for (int off = 128; off > 0; off >>= 1) {
        if (t < off) {
            ssh[t] += ssh[t + off]; sth[t] += sth[t + off];
            smx[t] = max(smx[t], smx[t + off]);
        }
        __syncthreads();
    }
    if (t == 0) {
        atomicAdd(&g_sameMass, ssh[0]);
        atomicAdd(&g_totMass, sth[0]);
        atomicMax(&g_maxA, smx[0]);
        __threadfence();
        if (atomicAdd(&g_tk[0], 1u) == gridDim.x - 1) {
            double sm = g_sameMass, tm = g_totMass;
            double dm = tm - sm;
            float cur = (float)(sm / tm);
            float ws = fminf(fmaxf(0.7f / (cur + 1e-6f), (float)(1.0 / 3.0)), 3.0f);
            float wd = fminf(fmaxf(0.3f / (1.0f - cur + 1e-6f), (float)(1.0 / 3.0)), 3.0f);
            g_wsame = ws; g_wdiff = wd;
            int skip = (sm <= 1e-6 || dm <= 1e-6 || fabsf(cur - 0.7f) <= 0.05f) ? 1 : 0;
            g_skip = skip;
            // diff-class pair key p <= RN(maxA*wd); if below pivot(2.0), no diff-class
            // pair can ever be a candidate -> provably skippable in pmatK.
            float maxA = __uint_as_float(g_maxA);
            g_dSkip = (!skip && __fmul_rn(maxA, wd) < 2.0f) ? 1 : 0;
        }
    }
}

__device__ __forceinline__ unsigned pivotBits(int skip) {
    return skip ? 0x3F666666u : 0x40000000u;   // 0.9f : 2.0f
}

// ---------------- P compute + candidate append (R6 grid + dSkip) ----------------
__global__ void pmatK(const float* __restrict__ adj) {
    int bi = blockIdx.y, bj = blockIdx.x;
    if (bj < bi) return;
    __shared__ float sAt[64][65];
    __shared__ unsigned char slj[64];
    __shared__ unsigned short sMask[64][4];
    __shared__ unsigned warpTot[8], warpBase[8];
    __shared__ unsigned blockBase;
    int t = threadIdx.x;
    const bool isDiag = (bi == bj);

    if (t < 64) slj[t] = g_labels8[bj * 64 + t];
    for (int e = t; e < 64 * 16; e += 256) {
        int r2 = e >> 4, c4 = (e & 15) * 4;
        float4 v = __ldcs((const float4*)(adj + (size_t)(bj * 64 + r2) * NDIM + bi * 64 + c4));
        sAt[r2][c4] = v.x; sAt[r2][c4 + 1] = v.y; sAt[r2][c4 + 2] = v.z; sAt[r2][c4 + 3] = v.w;
    }
    __syncthreads();
    {
        int r = t >> 2, q = t & 3;
        unsigned char lr = g_labels8[bi * 64 + r];
        unsigned short m = 0;
#pragma unroll
        for (int cc = 0; cc < 16; cc++)
            m |= (unsigned short)((lr == slj[q * 16 + cc]) ? 1 : 0) << cc;
        sMask[r][q] = m;
    }
    __syncthreads();
    int skip = g_skip;
    int dSkip = g_dSkip;
    float ws = g_wsame, wd = g_wdiff;
    unsigned lo = pivotBits(skip);
    unsigned long long loc[16];
    int cnt = 0;
    for (int e = t; e < 64 * 16; e += 256) {
        int r = e >> 4, c4 = (e & 15) * 4;
        unsigned nib = ((unsigned)sMask[r][c4 >> 4] >> (c4 & 15)) & 0xFu;
        if (dSkip && nib == 0u) continue;        // whole group provably below pivot: no load
        int i = bi * 64 + r;
        int j0 = bj * 64 + c4;
        float4 a = __ldcs((const float4*)(adj + (size_t)i * NDIM + j0));
        float av[4] = {a.x, a.y, a.z, a.w};
#pragma unroll
        for (int k = 0; k < 4; k++) {
            int j = j0 + k;
            if (isDiag && j <= i) continue;
            if (dSkip && !((nib >> k) & 1u)) continue;   // diff-class: provably below pivot
            float p;
            if (skip) p = av[k];
            else {
                float w = ((nib >> k) & 1u) ? ws : wd;
                p = 0.5f * __fadd_rn(__fmul_rn(av[k], w), __fmul_rn(sAt[c4 + k][r], w));
            }
            unsigned bits = __float_as_uint(p);
            if (bits >= lo)
                loc[cnt++] = ((unsigned long long)bits << 32) | (unsigned)(i * NDIM + j);
        }
    }
    unsigned pre = (unsigned)cnt;
    for (int d = 1; d < 32; d <<= 1) {
        unsigned v = __shfl_up_sync(0xFFFFFFFFu, pre, d);
        if ((t & 31) >= d) pre += v;
    }
    if ((t & 31) == 31) warpTot[t >> 5] = pre;
    __syncthreads();
    if (t == 0) {
        unsigned s = 0;
        for (int w = 0; w < 8; w++) { unsigned v = warpTot[w]; warpBase[w] = s; s += v; }
        blockBase = s ? atomicAdd(&g_bufCnt, s) : 0u;
    }
    __syncthreads();
    unsigned base = blockBase + warpBase[t >> 5] + (pre - (unsigned)cnt);
    for (int k = 0; k < cnt; k++) {
        unsigned pos = base + (unsigned)k;
        if (pos < BUF_CAP) g_buf[pos] = loc[k];
    }
}

// ---------------- edge emission ----------------
__device__ __forceinline__ void emitEdge(int i, int j, float p,
                                         const float* __restrict__ adj, int skip) {
    float pf_i, pr_i, pf_j, pr_j;
    if (skip) {
        float aij = adj[(size_t)i * NDIM + j];
        float aji = adj[(size_t)j * NDIM + i];
        pf_i = aij; pr_i = aji; pf_j = aji; pr_j = aij;
    } else {
        pf_i = pr_i = pf_j = pr_j = p;
    }
    int di = atomicAdd(&g_deg[i], 1);
    if (di < CAP) {
        size_t s = (size_t)i * CAP + di;
        g_nbr[s] = j; g_pf[s] = pf_i; g_pr[s] = pr_i; g_act[s] = 1;
    }
    int dj = atomicAdd(&g_deg[j], 1);
    if (dj < CAP) {
        size_t s = (size_t)j * CAP + dj;
        g_nbr[s] = i; g_pf[s] = pf_j; g_pr[s] = pr_j; g_act[s] = 1;
    }
}

// ---------------- persistent tail ----------------
__global__ void __launch_bounds__(1024, 1) postK(const float* __restrict__ adj) {
    __shared__ unsigned shH[4096];
    __shared__ unsigned sBA, sCntA, sBinB, sCntB, sBAB, sThr, sNeed;
    int t = threadIdx.x;
    if (t == 0) { sThr = 0xFFFFFFFFu; sNeed = 0u; }
    __syncthreads();

    // phase F: rare-path fallback — if pivot under-collected, append everything below it
    if (__ldcg(&g_bufCnt) < KSEL) {
        int skip = g_skip;
        float ws = g_wsame, wd = g_wdiff;
        unsigned lo = pivotBits(skip);
        for (int tile = blockIdx.x; tile < 128 * 128; tile += LOOP_BLOCKS) {
            int bi = tile >> 7, bj = tile & 127;
            if (bj < bi) continue;
            for (int e = t; e < 4096; e += 1024) {
                int i = bi * 64 + (e >> 6), j = bj * 64 + (e & 63);
                if (j <= i) continue;
                float a1 = adj[(size_t)i * NDIM + j];
                float p;
                if (skip) p = a1;
                else {
                    float a2 = adj[(size_t)j * NDIM + i];
                    float w = (g_labels8[i] == g_labels8[j]) ? ws : wd;
                    p = 0.5f * __fadd_rn(__fmul_rn(a1, w), __fmul_rn(a2, w));
                }
                unsigned bits = __float_as_uint(p);
                if (bits < lo) {
                    unsigned pos = atomicAdd(&g_bufCnt, 1u);
                    if (pos < BUF_CAP)
                        g_buf[pos] = ((unsigned long long)bits << 32) | (unsigned)(i * NDIM + j);
                }
            }
        }
    }
    gridBar();
    unsigned n = min(__ldcg(&g_bufCnt), BUF_CAP);

    // phase H1
    {
        for (int k = t; k < 4096; k += 1024) shH[k] = 0;
        __syncthreads();
        for (unsigned idx = blockIdx.x * 1024u + t; idx < n; idx += LOOP_BLOCKS * 1024u)
            atomicAdd(&shH[(unsigned)(__ldcg(&g_buf[idx]) >> 32) >> 20], 1u);
        __syncthreads();
        for (int k = t; k < 4096; k += 1024)
            if (shH[k]) atomicAdd(&g_hist1[k], shH[k]);
    }
    gridBar();
    scanSelect4096(g_hist1, 0u, &sBA, &sCntA);

    // phase H2
    {
        for (int k = t; k < 4096; k += 1024) shH[k] = 0;
        __syncthreads();
        unsigned bA = sBA;
        for (unsigned idx = blockIdx.x * 1024u + t; idx < n; idx += LOOP_BLOCKS * 1024u) {
            unsigned bits = (unsigned)(__ldcg(&g_buf[idx]) >> 32);
            if ((bits >> 20) == bA) atomicAdd(&shH[(bits >> 8) & 0xFFFu], 1u);
        }
        __syncthreads();
        for (int k = t; k < 4096; k += 1024)
            if (shH[k]) atomicAdd(&g_hist2[k], shH[k]);
    }
    gridBar();
    scanSelect4096(g_hist2, sCntA, &sBinB, &sCntB);
    if (t == 0) sBAB = (sBA << 12) | sBinB;
    __syncthreads();

    // phase H3
    {
        if (t < 256) shH[t] = 0;
        __syncthreads();
        unsigned bAB = sBAB;
        for (unsigned idx = blockIdx.x * 1024u + t; idx < n; idx += LOOP_BLOCKS * 1024u) {
            unsigned bits = (unsigned)(__ldcg(&g_buf[idx]) >> 32);
            if ((bits >> 8) == bAB) atomicAdd(&shH[bits & 0xFFu], 1u);
        }
        __syncthreads();
        if (t < 256 && shH[t]) atomicAdd(&g_hist3[t], shH[t]);
    }
    gridBar();
    scanSelect256(g_hist3, sCntB, sBAB, &sThr, &sNeed);

    // phase S: select + emit
    {
        unsigned thr = sThr;
        int skip = g_skip;
        for (unsigned idx = blockIdx.x * 1024u + t; idx < n; idx += LOOP_BLOCKS * 1024u) {
            unsigned long long e = __ldcg(&g_buf[idx]);
            unsigned bits = (unsigned)(e >> 32);
            if (bits > thr) {
                unsigned fi = (unsigned)e;
                emitEdge((int)(fi >> 13), (int)(fi & 8191u), __uint_as_float(bits), adj, skip);
            } else if (bits == thr) {
                unsigned pos = atomicAdd(&g_eqCnt, 1u);
                if (pos < KSEL) g_eqIdx[pos] = (unsigned)e;
            }
        }
    }
    gridBar();

    // phase T: tie resolution (lowest flat index wins); plain load of eqCnt (ordered by bar)
    {
        unsigned M = min(__ldcg(&g_eqCnt), KSEL);
        unsigned need = sNeed;
        unsigned thr = sThr;
        int skip = g_skip;
        if (need > 0) {
            for (unsigned u = blockIdx.x * 1024u + t; u < M; u += LOOP_BLOCKS * 1024u) {
                unsigned idx = __ldcg(&g_eqIdx[u]);
                unsigned rank = 0;
                for (unsigned s = 0; s < M; s++) rank += (__ldcg(&g_eqIdx[s]) < idx) ? 1u : 0u;
                if (rank < need)
                    emitEdge((int)(idx >> 13), (int)(idx & 8191u), __uint_as_float(thr), adj, skip);
            }
        }
    }
    gridBar();

    // phase P: degree-cap prune loop, warp per row, early exit on fixed point
    int lane = t & 31;
    int warpG = blockIdx.x * 32 + (t >> 5);
    const int nW = LOOP_BLOCKS * 32;
    __shared__ unsigned sCont;

    for (int iter = 0; iter < 10; iter++) {
        for (int i = warpG; i < NDIM; i += nW) {
            size_t base = (size_t)i * CAP;
            int degE = min(__ldcg(&g_deg[i]), CAP);
            float v[16]; unsigned am = 0, dc = 0;
#pragma unroll
            for (int k = 0; k < 16; k++) {
                int s = lane + k * 32;
                bool a = (s < degE) && (__ldcg(&g_act[base + s]) != 0);
                if (a) { v[k] = __ldcg(&g_pf[base + s]); am |= 1u << k; dc++; }
            }
            unsigned deg = __reduce_add_sync(0xFFFFFFFFu, dc);
            if (deg <= (unsigned)MAXDEG) {
                if (lane == 0) __stcg(&g_keepall[i], (unsigned char)1);
                continue;
            }
            if (lane == 0) __stcg(&g_keepall[i], (unsigned char)0);
            unsigned T = 0;
            for (int b = 31; b >= 0; b--) {
                unsigned cand = T | (1u << b);
                unsigned c = 0;
#pragma unroll
                for (int k = 0; k < 16; k++)
                    if (((am >> k) & 1u) && __float_as_uint(v[k]) >= cand) c++;
                c = __reduce_add_sync(0xFFFFFFFFu, c);
                if (c >= (unsigned)MAXDEG) T = cand;
            }
            if (lane == 0) __stcg(&g_thrU[i], T);
        }
        gridBar();
        bool removed = false;
        for (int i = warpG; i < NDIM; i += nW) {
            size_t base = (size_t)i * CAP;
            int degE = min(__ldcg(&g_deg[i]), CAP);
            unsigned kaI = __ldcg(&g_keepall[i]);
            unsigned thrI = __ldcg(&g_thrU[i]);
            for (int s = lane; s < degE; s += 32) {
                if (!__ldcg(&g_act[base + s])) continue;
                int j = __ldcg(&g_nbr[base + s]);
                bool ki = kaI || (__float_as_uint(__ldcg(&g_pf[base + s])) >= thrI);
                bool kj = __ldcg(&g_keepall[j]) ||
                          (__float_as_uint(__ldcg(&g_pr[base + s])) >= __ldcg(&g_thrU[j]));
                if (!(ki && kj)) { __stcg(&g_act[base + s], (unsigned char)0); removed = true; }
            }
        }
        if (__any_sync(0xFFFFFFFFu, removed) && lane == 0)
            atomicOr(&g_changedArr[iter + 1], 1u);
        gridBar();
        if (t == 0) sCont = __ldcg(&g_changedArr[iter + 1]);
        __syncthreads();
        if (!sCont) break;
    }
}

// ---------------- fused zero + scatter output ----------------
__global__ void outK(float* __restrict__ out) {
    __shared__ unsigned sBits[256];
    int i = blockIdx.x, t = threadIdx.x;
    sBits[t] = 0;
    __syncthreads();
    size_t base = (size_t)i * CAP;
    int degE = min(g_deg[i], CAP);
    for (int s = t; s < degE; s += 256)
        if (g_act[base + s]) {
            int j = g_nbr[base + s];
            atomicOr(&sBits[j >> 5], 1u << (j & 31));
        }
    __syncthreads();
    float4* orow = (float4*)(out + (size_t)i * NDIM);
    for (int q = t; q < NDIM / 4; q += 256) {
        unsigned w = sBits[q >> 3];
        unsigned sh = (q & 7) * 4;
        float4 v;
        v.x = (w >> sh & 1u) ? 1.f : 0.f;
        v.y = (w >> (sh + 1) & 1u) ? 1.f : 0.f;
        v.z = (w >> (sh + 2) & 1u) ? 1.f : 0.f;
        v.w = (w >> (sh + 3) & 1u) ? 1.f : 0.f;
        __stcs(&orow[q], v);
    }
}

// ---------------- launch ----------------
extern "C" void kernel_launch(void* const* d_in, const int* in_sizes, int n_in,
                              void* d_out, int out_size) {
    const float* adj = (const float*)d_in[0];
    const float* lp  = (const float*)d_in[1];
    float* out = (float*)d_out;

    initK<<<33, 256>>>(lp);                    // clear + argmax fused
    massK<<<NDIM, 256>>>(adj);                 // + maxA + decide (last block)
    {
        dim3 grid(128, 128);
        pmatK<<<grid, 256>>>(adj);             // candidates; diff-class provably skipped
    }
    postK<<<LOOP_BLOCKS, 1024>>>(adj);         // fallback + radix + select + ties + prune
    outK<<<NDIM, 256>>>(out);
}